// round 6
// baseline (speedup 1.0000x reference)
#include <cuda_runtime.h>
#include <cstdint>

#define NUM_HEADS 8
#define IN_BITS   64
#define N_STATE   256
#define N_OUT     64
#define K_CONN    8
#define HASH      65536
#define BATCH     128
#define T_STEPS   128
#define TOTAL_IN  320   // IN_BITS + N_STATE

// Bit-packed threshold table: bit = (state_mem[n][a] >= 0.5). 2 MB, L2-resident.
__device__ uint32_t g_state_bits[N_STATE * (HASH / 32)];

#define PACK_LO(v) ((uint32_t)((v).x & 255) | ((uint32_t)((v).y & 255) << 8) \
                  | ((uint32_t)((v).z & 255) << 16) | ((uint32_t)((v).w & 255) << 24))
#define PACK_HI(v) ((uint32_t)(((v).x >> 8) & 255) | ((uint32_t)(((v).y >> 8) & 255) << 8) \
                  | ((uint32_t)(((v).z >> 8) & 255) << 16) | ((uint32_t)(((v).w >> 8) & 255) << 24))

// ---------------------------------------------------------------------------
// Prologue: pack state_mem (64 MB floats) into g_state_bits (2 MB). HBM-bound.
// ---------------------------------------------------------------------------
__global__ void pack_state_mem_kernel(const float* __restrict__ sm)
{
    const int tid  = blockIdx.x * blockDim.x + threadIdx.x;
    const int lane = threadIdx.x & 31;
    const int gw   = tid >> 5;
    const size_t base = (size_t)gw * 128;
    #pragma unroll
    for (int j = 0; j < 4; j++) {
        float v = sm[base + (size_t)j * 32 + lane];
        uint32_t b = __ballot_sync(0xFFFFFFFFu, v >= 0.5f);
        if (lane == 0) g_state_bits[gw * 4 + j] = b;
    }
}

// D += A * B  (m16n8k32, u8 x u8 -> s32)
#define MMA_U8(D, A, b0, b1)                                                   \
    asm volatile("mma.sync.aligned.m16n8k32.row.col.s32.u8.u8.s32 "            \
                 "{%0,%1,%2,%3}, {%4,%5,%6,%7}, {%8,%9}, {%0,%1,%2,%3};"       \
                 : "+r"((D)[0]), "+r"((D)[1]), "+r"((D)[2]), "+r"((D)[3])      \
                 : "r"((A)[0]), "r"((A)[1]), "r"((A)[2]), "r"((A)[3]),         \
                   "r"(b0), "r"(b1));

// ---------------------------------------------------------------------------
// Main scan. One CTA per batch, 256 threads (8 warps). Warp w owns neurons
// [w*32, w*32+32) as two 16-row MMA tiles; coefficients live in registers as
// A-fragments (lo/hi bytes of each 16-bit coeff -> two mma per K-chunk).
// x = [window(64B) | state(256B)] feeds B column 0 (lanes 0-3). Per step:
// 40 mma -> 4 sums on lanes with tig==0 -> 4 L2 gathers -> state bytes ->
// one barrier. addr = (lo + hi<<8) & 0xFFFF is exact mod-2^16.
// ---------------------------------------------------------------------------
__global__ __launch_bounds__(256, 1)
void ram_scan_kernel(const int*   __restrict__ bits,          // (B, T*64)
                     const int*   __restrict__ state_coeffs,  // (256, 320)
                     const int*   __restrict__ head_conn,     // (8, 64, 8)
                     const int*   __restrict__ head_coeffs,   // (8, 64, 8)
                     const float* __restrict__ head_mem,      // (8, 64, 65536)
                     float*       __restrict__ out)           // (B, 64)
{
    __shared__ uint32_t win_words[T_STEPS * 16];  // 8 KB: window bits as bytes
    __shared__ uint32_t stbuf[2][64];             // double-buffered 256 state bytes

    const int b    = blockIdx.x;
    const int t    = threadIdx.x;
    const int lane = t & 31;
    const int wb   = (t >> 5) * 32;               // warp's neuron base
    const int g    = lane >> 2;                   // groupID
    const int tig  = lane & 3;                    // thread-in-group

    // ---- expand all T windows to 0/1 bytes ----
    const int4* bits4 = reinterpret_cast<const int4*>(bits + (size_t)b * (T_STEPS * IN_BITS));
    for (int w = t; w < T_STEPS * 16; w += 256) {
        int4 v = bits4[w];
        win_words[w] = (uint32_t)(v.x & 1) | ((uint32_t)(v.y & 1) << 8)
                     | ((uint32_t)(v.z & 1) << 16) | ((uint32_t)(v.w & 1) << 24);
    }
    if (t < 64) stbuf[0][t] = 0u;

    // ---- A fragments: Alo/Ahi[tile][chunk][reg] per PTX m16n8k32 layout ----
    // a0:(row g,      k tig*4)  a1:(row g+8, k tig*4)
    // a2:(row g,      k+16)     a3:(row g+8, k+16)
    uint32_t Alo[2][10][4], Ahi[2][10][4];
    #pragma unroll
    for (int m = 0; m < 2; m++) {
        #pragma unroll
        for (int c = 0; c < 10; c++) {
            const int row0 = wb + m * 16 + g;
            const int k0   = c * 32 + tig * 4;
            int4 v00 = *reinterpret_cast<const int4*>(state_coeffs + (size_t)row0 * TOTAL_IN + k0);
            int4 v10 = *reinterpret_cast<const int4*>(state_coeffs + (size_t)(row0 + 8) * TOTAL_IN + k0);
            int4 v01 = *reinterpret_cast<const int4*>(state_coeffs + (size_t)row0 * TOTAL_IN + k0 + 16);
            int4 v11 = *reinterpret_cast<const int4*>(state_coeffs + (size_t)(row0 + 8) * TOTAL_IN + k0 + 16);
            Alo[m][c][0] = PACK_LO(v00); Ahi[m][c][0] = PACK_HI(v00);
            Alo[m][c][1] = PACK_LO(v10); Ahi[m][c][1] = PACK_HI(v10);
            Alo[m][c][2] = PACK_LO(v01); Ahi[m][c][2] = PACK_HI(v01);
            Alo[m][c][3] = PACK_LO(v11); Ahi[m][c][3] = PACK_HI(v11);
        }
    }
    __syncthreads();

    const uint8_t* winb = reinterpret_cast<const uint8_t*>(win_words);

    #pragma unroll 2
    for (int step = 0; step < T_STEPS; step++) {
        const int cur = step & 1, nxt = cur ^ 1;
        const uint8_t* xw = winb + step * 64;
        const uint8_t* xs = reinterpret_cast<const uint8_t*>(stbuf[cur]);

        // 8 accumulator chains: [tile][lo/hi][parity], 4 regs each
        uint32_t D[2][2][2][4];
        #pragma unroll
        for (int m = 0; m < 2; m++)
            #pragma unroll
            for (int p = 0; p < 2; p++)
                #pragma unroll
                for (int e = 0; e < 2; e++)
                    D[m][p][e][0] = D[m][p][e][1] = D[m][p][e][2] = D[m][p][e][3] = 0u;

        #pragma unroll
        for (int c = 0; c < 10; c++) {
            uint32_t b0 = 0u, b1 = 0u;
            if (lane < 4) {   // B column 0: k = lane*4..+3 (b0), +16 (b1)
                const uint8_t* src = (c < 2) ? (xw + c * 32) : (xs + (c - 2) * 32);
                b0 = *reinterpret_cast<const uint32_t*>(src + lane * 4);
                b1 = *reinterpret_cast<const uint32_t*>(src + 16 + lane * 4);
            }
            MMA_U8(D[0][0][c & 1], Alo[0][c], b0, b1);
            MMA_U8(D[0][1][c & 1], Ahi[0][c], b0, b1);
            MMA_U8(D[1][0][c & 1], Alo[1][c], b0, b1);
            MMA_U8(D[1][1][c & 1], Ahi[1][c], b0, b1);
        }

        if (tig == 0) {   // lanes 0,4,..,28 hold column 0: d0=(g), d2=(g+8)
            const uint32_t lo0 = D[0][0][0][0] + D[0][0][1][0];
            const uint32_t hi0 = D[0][1][0][0] + D[0][1][1][0];
            const uint32_t lo1 = D[0][0][0][2] + D[0][0][1][2];
            const uint32_t hi1 = D[0][1][0][2] + D[0][1][1][2];
            const uint32_t lo2 = D[1][0][0][0] + D[1][0][1][0];
            const uint32_t hi2 = D[1][1][0][0] + D[1][1][1][0];
            const uint32_t lo3 = D[1][0][0][2] + D[1][0][1][2];
            const uint32_t hi3 = D[1][1][0][2] + D[1][1][1][2];
            const uint32_t a0 = (lo0 + (hi0 << 8)) & 0xFFFFu;   // neuron wb+g
            const uint32_t a1 = (lo1 + (hi1 << 8)) & 0xFFFFu;   // wb+8+g
            const uint32_t a2 = (lo2 + (hi2 << 8)) & 0xFFFFu;   // wb+16+g
            const uint32_t a3 = (lo3 + (hi3 << 8)) & 0xFFFFu;   // wb+24+g
            const int n0 = wb + g, n1 = n0 + 8, n2 = n0 + 16, n3 = n0 + 24;
            const uint32_t w0 = __ldg(g_state_bits + ((size_t)n0 << 11) + (a0 >> 5));
            const uint32_t w1 = __ldg(g_state_bits + ((size_t)n1 << 11) + (a1 >> 5));
            const uint32_t w2 = __ldg(g_state_bits + ((size_t)n2 << 11) + (a2 >> 5));
            const uint32_t w3 = __ldg(g_state_bits + ((size_t)n3 << 11) + (a3 >> 5));
            uint8_t* stn = reinterpret_cast<uint8_t*>(stbuf[nxt]);
            stn[n0] = (uint8_t)((w0 >> (a0 & 31u)) & 1u);
            stn[n1] = (uint8_t)((w1 >> (a1 & 31u)) & 1u);
            stn[n2] = (uint8_t)((w2 >> (a2 & 31u)) & 1u);
            stn[n3] = (uint8_t)((w3 >> (a3 & 31u)) & 1u);
        }
        __syncthreads();
    }

    // ---- Head readout (threads 0..63); T even -> final state in stbuf[0] ----
    if (t < N_OUT) {
        const uint8_t* state_b = reinterpret_cast<const uint8_t*>(stbuf[0]);
        const int* lw = bits + (size_t)b * (T_STEPS * IN_BITS) + (T_STEPS * IN_BITS - 3);
        const int hidx = (lw[0] << 2) + (lw[1] << 1) + lw[2];    // 0..7
        const int o    = t;
        const int base = (hidx * N_OUT + o) * K_CONN;
        uint32_t addr = 0u;
        #pragma unroll
        for (int k = 0; k < K_CONN; k++) {
            int conn = __ldg(head_conn + base + k);
            uint32_t c = (uint32_t)__ldg(head_coeffs + base + k);
            addr += state_b[conn] ? c : 0u;
        }
        addr &= 0xFFFFu;
        out[(size_t)b * N_OUT + o] =
            __ldg(head_mem + (((size_t)(hidx * N_OUT + o)) << 16) + addr);
    }
}

extern "C" void kernel_launch(void* const* d_in, const int* in_sizes, int n_in,
                              void* d_out, int out_size)
{
    const int*   bits         = (const int*)  d_in[0];
    const int*   state_coeffs = (const int*)  d_in[1];
    const float* state_mem    = (const float*)d_in[2];
    const int*   head_conn    = (const int*)  d_in[3];
    const int*   head_coeffs  = (const int*)  d_in[4];
    const float* head_mem     = (const float*)d_in[5];
    float*       out          = (float*)      d_out;

    pack_state_mem_kernel<<<16384, 256>>>(state_mem);
    ram_scan_kernel<<<BATCH, 256>>>(bits, state_coeffs,
                                    head_conn, head_coeffs, head_mem, out);
}

// round 7
// speedup vs baseline: 3.5599x; 3.5599x over previous
#include <cuda_runtime.h>
#include <cstdint>

#define NUM_HEADS 8
#define IN_BITS   64
#define N_STATE   256
#define N_OUT     64
#define K_CONN    8
#define HASH      65536
#define BATCH     128
#define T_STEPS   128
#define TOTAL_IN  320   // IN_BITS + N_STATE

// Bit-packed threshold table: bit = (state_mem[n][a] >= 0.5). 2 MB, L2-resident.
__device__ uint32_t g_state_bits[N_STATE * (HASH / 32)];

// ---------------------------------------------------------------------------
// Prologue: pack state_mem (64 MB floats) into g_state_bits (2 MB). HBM-bound.
// ---------------------------------------------------------------------------
__global__ void pack_state_mem_kernel(const float* __restrict__ sm)
{
    const int tid  = blockIdx.x * blockDim.x + threadIdx.x;
    const int lane = threadIdx.x & 31;
    const int gw   = tid >> 5;
    const size_t base = (size_t)gw * 128;
    #pragma unroll
    for (int j = 0; j < 4; j++) {
        float v = sm[base + (size_t)j * 32 + lane];
        uint32_t b = __ballot_sync(0xFFFFFFFFu, v >= 0.5f);
        if (lane == 0) g_state_bits[gw * 4 + j] = b;
    }
}

// ---------------------------------------------------------------------------
// Main scan. One CTA per batch, 512 threads (16 warps).
// Thread t: neuron n = t>>1, half h = t&1. Half h owns x bytes
// [h*160, h*160+160) of the unified per-step vector x = [window | state].
// Coefficients: 160 16-bit values packed as 80 u32 (2 coeffs each), used by
// dp2a (16b x 8b dot-2) with a single exact u32 accumulator set.
// Per step: 10 LDS.128 + 80 dp2a + shfl_xor(1) + (even lanes) 1 L2 gather +
// state-byte STS + window prefill + ONE barrier.
// ---------------------------------------------------------------------------
__global__ __launch_bounds__(512, 1)
void ram_scan_kernel(const int*   __restrict__ bits,          // (B, T*64)
                     const int*   __restrict__ state_coeffs,  // (256, 320)
                     const int*   __restrict__ head_conn,     // (8, 64, 8)
                     const int*   __restrict__ head_coeffs,   // (8, 64, 8)
                     const float* __restrict__ head_mem,      // (8, 64, 65536)
                     float*       __restrict__ out)           // (B, 64)
{
    __shared__ uint32_t win_words[T_STEPS * 16]; // 8 KB: all window bits as bytes
    __shared__ uint32_t xbuf[2][96];             // 2 x 384 B: [win 16w | state 64w | pad]

    const int b = blockIdx.x;
    const int t = threadIdx.x;
    const int n = t >> 1;          // neuron
    const int h = t & 1;           // half

    // ---- expand all T windows to 0/1 bytes ----
    const int4* bits4 = reinterpret_cast<const int4*>(bits + (size_t)b * (T_STEPS * IN_BITS));
    for (int w = t; w < T_STEPS * 16; w += 512) {
        int4 v = bits4[w];
        win_words[w] = (uint32_t)(v.x & 1) | ((uint32_t)(v.y & 1) << 8)
                     | ((uint32_t)(v.z & 1) << 16) | ((uint32_t)(v.w & 1) << 24);
    }

    // ---- coefficients: 160 16-bit values -> 80 packed u32 ----
    uint32_t c2[80];
    {
        const int4* crow = reinterpret_cast<const int4*>(
            state_coeffs + (size_t)n * TOTAL_IN + h * 160);
        #pragma unroll
        for (int j = 0; j < 40; j++) {
            int4 v = crow[j];
            c2[2*j]   = (uint32_t)(v.x & 0xFFFF) | ((uint32_t)v.y << 16);
            c2[2*j+1] = (uint32_t)(v.z & 0xFFFF) | ((uint32_t)v.w << 16);
        }
    }
    __syncthreads();   // win_words ready

    // ---- init xbuf[0] = [window(step 0) | zero state] ----
    if (t < 16)                 xbuf[0][t] = win_words[t];
    else if (t < 80)            xbuf[0][t] = 0u;
    __syncthreads();

    const uint32_t* prow = g_state_bits + ((size_t)n << 11);   // 2048 words/row

    #pragma unroll 2
    for (int step = 0; step < T_STEPS; step++) {
        const int cur = step & 1, nxt = cur ^ 1;
        const uint4* xv = reinterpret_cast<const uint4*>(xbuf[cur]) + h * 10;

        // 160-input half-dot: 80 dp2a, 4 accumulator chains
        uint32_t a0 = 0u, a1 = 0u, a2 = 0u, a3 = 0u;
        #pragma unroll
        for (int j = 0; j < 10; j += 2) {
            uint4 x0 = xv[j];
            uint4 x1 = xv[j + 1];
            a0 = __dp2a_lo(c2[8*j+0], x0.x, a0); a0 = __dp2a_hi(c2[8*j+1], x0.x, a0);
            a1 = __dp2a_lo(c2[8*j+2], x0.y, a1); a1 = __dp2a_hi(c2[8*j+3], x0.y, a1);
            a2 = __dp2a_lo(c2[8*j+4], x0.z, a2); a2 = __dp2a_hi(c2[8*j+5], x0.z, a2);
            a3 = __dp2a_lo(c2[8*j+6], x0.w, a3); a3 = __dp2a_hi(c2[8*j+7], x0.w, a3);
            a0 = __dp2a_lo(c2[8*j+8], x1.x, a0); a0 = __dp2a_hi(c2[8*j+9], x1.x, a0);
            a1 = __dp2a_lo(c2[8*j+10], x1.y, a1); a1 = __dp2a_hi(c2[8*j+11], x1.y, a1);
            a2 = __dp2a_lo(c2[8*j+12], x1.z, a2); a2 = __dp2a_hi(c2[8*j+13], x1.z, a2);
            a3 = __dp2a_lo(c2[8*j+14], x1.w, a3); a3 = __dp2a_hi(c2[8*j+15], x1.w, a3);
        }
        uint32_t s = (a0 + a1) + (a2 + a3);
        s += __shfl_xor_sync(0xFFFFFFFFu, s, 1);   // combine halves

        // even lane: random gather (L2-resident 2 MB) + state byte for step+1
        uint32_t wword = 0u, addr = s & 0xFFFFu;
        if (h == 0) wword = __ldg(prow + (addr >> 5));

        // window prefill for step+1 in the gather's shadow
        if (t < 16)
            xbuf[nxt][t] = win_words[((((step + 1) & (T_STEPS - 1))) << 4) + t];

        if (h == 0)
            reinterpret_cast<uint8_t*>(xbuf[nxt])[64 + n] =
                (uint8_t)((wword >> (addr & 31u)) & 1u);

        __syncthreads();   // next x ready; old buffer free
    }

    // ---- Head readout (threads 0..63); final state in xbuf[0] bytes 64.. ----
    if (t < N_OUT) {
        const uint8_t* state_b = reinterpret_cast<const uint8_t*>(xbuf[0]) + 64;
        const int* lw = bits + (size_t)b * (T_STEPS * IN_BITS) + (T_STEPS * IN_BITS - 3);
        const int hidx = (lw[0] << 2) + (lw[1] << 1) + lw[2];    // 0..7
        const int o    = t;
        const int base = (hidx * N_OUT + o) * K_CONN;
        uint32_t addr = 0u;
        #pragma unroll
        for (int k = 0; k < K_CONN; k++) {
            int conn = __ldg(head_conn + base + k);
            uint32_t c = (uint32_t)__ldg(head_coeffs + base + k);
            addr += state_b[conn] ? c : 0u;
        }
        addr &= 0xFFFFu;
        out[(size_t)b * N_OUT + o] =
            __ldg(head_mem + (((size_t)(hidx * N_OUT + o)) << 16) + addr);
    }
}

extern "C" void kernel_launch(void* const* d_in, const int* in_sizes, int n_in,
                              void* d_out, int out_size)
{
    const int*   bits         = (const int*)  d_in[0];
    const int*   state_coeffs = (const int*)  d_in[1];
    const float* state_mem    = (const float*)d_in[2];
    const int*   head_conn    = (const int*)  d_in[3];
    const int*   head_coeffs  = (const int*)  d_in[4];
    const float* head_mem     = (const float*)d_in[5];
    float*       out          = (float*)      d_out;

    pack_state_mem_kernel<<<16384, 256>>>(state_mem);
    ram_scan_kernel<<<BATCH, 512>>>(bits, state_coeffs,
                                    head_conn, head_coeffs, head_mem, out);
}

// round 8
// speedup vs baseline: 3.7135x; 1.0432x over previous
#include <cuda_runtime.h>
#include <cstdint>

#define NUM_HEADS 8
#define IN_BITS   64
#define N_STATE   256
#define N_OUT     64
#define K_CONN    8
#define HASH      65536
#define BATCH     128
#define T_STEPS   128
#define TOTAL_IN  320   // IN_BITS + N_STATE

// Bit-packed threshold table: bit = (state_mem[n][a] >= 0.5). 2 MB, L2-resident.
__device__ uint32_t g_state_bits[N_STATE * (HASH / 32)];

// ---------------------------------------------------------------------------
// Prologue: pack state_mem (64 MB floats) into g_state_bits (2 MB). HBM-bound.
// ---------------------------------------------------------------------------
__global__ void pack_state_mem_kernel(const float* __restrict__ sm)
{
    const int tid  = blockIdx.x * blockDim.x + threadIdx.x;
    const int lane = threadIdx.x & 31;
    const int gw   = tid >> 5;
    const size_t base = (size_t)gw * 128;
    #pragma unroll
    for (int j = 0; j < 4; j++) {
        float v = sm[base + (size_t)j * 32 + lane];
        uint32_t b = __ballot_sync(0xFFFFFFFFu, v >= 0.5f);
        if (lane == 0) g_state_bits[gw * 4 + j] = b;
    }
}

// ---------------------------------------------------------------------------
// Main scan. One CTA per batch, 256 threads, thread t = neuron t.
// Coefficients register-resident as native u16 pairs for dp2a (exact u32
// accumulation; addr = sum & 0xFFFF is exact mod 2^16).
// Per step:
//   state dot (128 dp2a) -> addr -> LDG (L2-resident bit table)
//   [gather shadow] window dot for step+1 (32 dp2a)
//   g0 (t<128): extract+store state byte; bar1  (g1 arrives early)
//   g1 (t>=128): extract+store (word arrived during bar1 wait); bar2
// Split barriers pipeline the L1tex drain of 256 divergent gathers.
// ---------------------------------------------------------------------------
__global__ __launch_bounds__(256, 1)
void ram_scan_kernel(const int*   __restrict__ bits,          // (B, T*64)
                     const int*   __restrict__ state_coeffs,  // (256, 320)
                     const int*   __restrict__ head_conn,     // (8, 64, 8)
                     const int*   __restrict__ head_coeffs,   // (8, 64, 8)
                     const float* __restrict__ head_mem,      // (8, 64, 65536)
                     float*       __restrict__ out)           // (B, 64)
{
    __shared__ uint32_t win_words[T_STEPS * 16]; // 8 KB: all window bits as bytes
    __shared__ uint32_t stbuf[2][64];            // double-buffered 256 state bytes

    const int b = blockIdx.x;
    const int t = threadIdx.x;                   // neuron id

    // ---- expand all T windows to 0/1 bytes ----
    const int4* bits4 = reinterpret_cast<const int4*>(bits + (size_t)b * (T_STEPS * IN_BITS));
    for (int w = t; w < T_STEPS * 16; w += 256) {
        int4 v = bits4[w];
        win_words[w] = (uint32_t)(v.x & 1) | ((uint32_t)(v.y & 1) << 8)
                     | ((uint32_t)(v.z & 1) << 16) | ((uint32_t)(v.w & 1) << 24);
    }
    if (t < 64) stbuf[0][t] = 0u;   // initial state = 0

    // ---- coefficients: window 64 -> 32 packed u32, state 256 -> 128 packed ----
    uint32_t w2[32], c2[128];
    {
        const int4* crow = reinterpret_cast<const int4*>(state_coeffs + (size_t)t * TOTAL_IN);
        #pragma unroll
        for (int k = 0; k < 16; k++) {
            int4 v = crow[k];
            w2[2*k]   = (uint32_t)(v.x & 0xFFFF) | ((uint32_t)v.y << 16);
            w2[2*k+1] = (uint32_t)(v.z & 0xFFFF) | ((uint32_t)v.w << 16);
        }
        #pragma unroll
        for (int k = 0; k < 64; k++) {
            int4 v = crow[16 + k];
            c2[2*k]   = (uint32_t)(v.x & 0xFFFF) | ((uint32_t)v.y << 16);
            c2[2*k+1] = (uint32_t)(v.z & 0xFFFF) | ((uint32_t)v.w << 16);
        }
    }
    __syncthreads();   // win_words + stbuf[0] ready

    const uint4* wv = reinterpret_cast<const uint4*>(win_words); // 4 uint4 / step

    // window dot for a given step: 32 dp2a over 4 uint4
    #define WIN_ACC(STEP, OUTV)                                                 \
    {                                                                           \
        uint32_t _a0 = 0u, _a1 = 0u, _a2 = 0u, _a3 = 0u;                        \
        _Pragma("unroll")                                                       \
        for (int q = 0; q < 4; q++) {                                           \
            uint4 x = wv[(STEP) * 4 + q];                                       \
            _a0 = __dp2a_lo(w2[8*q+0], x.x, _a0); _a0 = __dp2a_hi(w2[8*q+1], x.x, _a0); \
            _a1 = __dp2a_lo(w2[8*q+2], x.y, _a1); _a1 = __dp2a_hi(w2[8*q+3], x.y, _a1); \
            _a2 = __dp2a_lo(w2[8*q+4], x.z, _a2); _a2 = __dp2a_hi(w2[8*q+5], x.z, _a2); \
            _a3 = __dp2a_lo(w2[8*q+6], x.w, _a3); _a3 = __dp2a_hi(w2[8*q+7], x.w, _a3); \
        }                                                                       \
        (OUTV) = (_a0 + _a1) + (_a2 + _a3);                                     \
    }

    uint32_t wacc;
    WIN_ACC(0, wacc);

    const uint32_t* prow = g_state_bits + ((size_t)t << 11);   // 2048 words/row

    #pragma unroll 2
    for (int step = 0; step < T_STEPS; step++) {
        const int cur = step & 1, nxt = cur ^ 1;
        const uint4* st4 = reinterpret_cast<const uint4*>(stbuf[cur]);

        // state dot: 256 inputs = 128 dp2a, 4 accumulator chains
        uint32_t a0 = 0u, a1 = 0u, a2 = 0u, a3 = 0u;
        #pragma unroll
        for (int q = 0; q < 16; q++) {
            uint4 x = st4[q];
            a0 = __dp2a_lo(c2[8*q+0], x.x, a0); a0 = __dp2a_hi(c2[8*q+1], x.x, a0);
            a1 = __dp2a_lo(c2[8*q+2], x.y, a1); a1 = __dp2a_hi(c2[8*q+3], x.y, a1);
            a2 = __dp2a_lo(c2[8*q+4], x.z, a2); a2 = __dp2a_hi(c2[8*q+5], x.z, a2);
            a3 = __dp2a_lo(c2[8*q+6], x.w, a3); a3 = __dp2a_hi(c2[8*q+7], x.w, a3);
        }
        const uint32_t s    = (a0 + a1) + (a2 + a3) + wacc;
        const uint32_t addr = s & 0xFFFFu;

        // random gather (L2-resident 2 MB table)
        const uint32_t wword = __ldg(prow + (addr >> 5));

        // gather shadow: window dot for the next step (state-independent)
        uint32_t wnext;
        WIN_ACC((step + 1) & (T_STEPS - 1), wnext);

        uint8_t* stn = reinterpret_cast<uint8_t*>(stbuf[nxt]);
        if (t < 128)   // group 0: consume own gather, store byte, then bar1
            stn[t] = (uint8_t)((wword >> (addr & 31u)) & 1u);
        __syncthreads();   // bar1: g0 bytes visible; g1 arrived early
        if (t >= 128)  // group 1: word arrived during bar1 wait
            stn[t] = (uint8_t)((wword >> (addr & 31u)) & 1u);
        __syncthreads();   // bar2: full next state visible; old buffer free
        wacc = wnext;
    }

    // ---- Head readout (threads 0..63); T even -> final state in stbuf[0] ----
    if (t < N_OUT) {
        const uint8_t* state_b = reinterpret_cast<const uint8_t*>(stbuf[0]);
        const int* lw = bits + (size_t)b * (T_STEPS * IN_BITS) + (T_STEPS * IN_BITS - 3);
        const int hidx = (lw[0] << 2) + (lw[1] << 1) + lw[2];    // 0..7
        const int o    = t;
        const int base = (hidx * N_OUT + o) * K_CONN;
        uint32_t addr = 0u;
        #pragma unroll
        for (int k = 0; k < K_CONN; k++) {
            int conn = __ldg(head_conn + base + k);
            uint32_t c = (uint32_t)__ldg(head_coeffs + base + k);
            addr += state_b[conn] ? c : 0u;
        }
        addr &= 0xFFFFu;
        out[(size_t)b * N_OUT + o] =
            __ldg(head_mem + (((size_t)(hidx * N_OUT + o)) << 16) + addr);
    }
    #undef WIN_ACC
}

extern "C" void kernel_launch(void* const* d_in, const int* in_sizes, int n_in,
                              void* d_out, int out_size)
{
    const int*   bits         = (const int*)  d_in[0];
    const int*   state_coeffs = (const int*)  d_in[1];
    const float* state_mem    = (const float*)d_in[2];
    const int*   head_conn    = (const int*)  d_in[3];
    const int*   head_coeffs  = (const int*)  d_in[4];
    const float* head_mem     = (const float*)d_in[5];
    float*       out          = (float*)      d_out;

    pack_state_mem_kernel<<<16384, 256>>>(state_mem);
    ram_scan_kernel<<<BATCH, 256>>>(bits, state_coeffs,
                                    head_conn, head_coeffs, head_mem, out);
}